// round 8
// baseline (speedup 1.0000x reference)
#include <cuda_runtime.h>
#include <cuda_fp16.h>
#include <cstdint>

// ---------------- problem sizes ----------------
#define BB   16
#define CI   512
#define CO   512
#define HW_  64
#define DL   512
#define HPAD 66

#define C_LIN  0.044194173824159216f   // 1/sqrt(512)
#define C_CONV 0.014731391274719739f   // 1/sqrt(512*9)

// ---------------- device scratch ----------------
__device__ __half g_wh[9 * CO * CI];                   // weights fp16, tap-major [9][CO][CI]
__device__ float  g_wsq[CO * CI];                      // sum_k conv_w^2
__device__ float  g_z0[BB * DL];
__device__ float  g_z1[BB * DL];
__device__ float  g_style[BB * CI];
__device__ float  g_sout[BB * CO];                     // c_conv * sigma_inv
__device__ __half g_xp[(size_t)BB * HPAD * HPAD * CI]; // NHWC padded modulated input

// ---------------- helpers ----------------
__device__ __forceinline__ uint32_t smem_u32(const void* p) {
    uint32_t a;
    asm("{ .reg .u64 t; cvta.to.shared.u64 t, %1; cvt.u32.u64 %0, t; }" : "=r"(a) : "l"(p));
    return a;
}

__device__ __forceinline__ uint32_t swz(uint32_t x) { return x ^ ((x >> 3) & 0x70); }

#define CP16(smem, gptr) \
    asm volatile("cp.async.cg.shared.global [%0], [%1], 16;" :: "r"(smem), "l"(gptr))
#define CP_COMMIT() asm volatile("cp.async.commit_group;" ::: "memory")
#define CP_WAIT(n)  asm volatile("cp.async.wait_group %0;" :: "n"(n) : "memory")

__device__ __forceinline__ void ldsm_x4(uint32_t& r0, uint32_t& r1, uint32_t& r2, uint32_t& r3,
                                        uint32_t addr) {
    asm volatile("ldmatrix.sync.aligned.m8n8.x4.shared.b16 {%0,%1,%2,%3}, [%4];"
                 : "=r"(r0), "=r"(r1), "=r"(r2), "=r"(r3) : "r"(addr));
}

__device__ __forceinline__ void mma16816(float* c, const uint32_t* a, uint32_t b0, uint32_t b1) {
    asm volatile(
        "mma.sync.aligned.m16n8k16.row.col.f32.f16.f16.f32 "
        "{%0,%1,%2,%3}, {%4,%5,%6,%7}, {%8,%9}, {%0,%1,%2,%3};"
        : "+f"(c[0]), "+f"(c[1]), "+f"(c[2]), "+f"(c[3])
        : "r"(a[0]), "r"(a[1]), "r"(a[2]), "r"(a[3]), "r"(b0), "r"(b1));
}

// ---------------- kernel A: linear layer (32 blocks) + optional weight prep ----------------
__global__ void lin_wp(const float* __restrict__ ext_in, const float* __restrict__ W,
                       const float* __restrict__ bias, const float* __restrict__ pa,
                       const float* __restrict__ cw, int mode) {
    int bid = blockIdx.x;
    int tid = threadIdx.x;  // 256
    if (bid >= 32) {
        int g = (bid - 32) * 256 + tid;
        const float* p = cw + (size_t)g * 9;
        float sq = 0.f;
#pragma unroll
        for (int k = 0; k < 9; k++) {
            float v = p[k];
            sq = fmaf(v, v, sq);
            g_wh[(size_t)k * (CO * CI) + g] = __float2half(v);
        }
        g_wsq[g] = sq;
        return;
    }
    __shared__ float sin_t[DL * BB];   // transposed [j][b], 32KB
    const float* in = (mode == 0) ? ext_in : (mode == 1 ? g_z0 : g_z1);
    float* out      = (mode == 0) ? g_z0   : (mode == 1 ? g_z1 : g_style);
#pragma unroll
    for (int t = 0; t < 8; t++) {
        int idx = tid + t * 256;
        int b = idx & 15, j4 = idx >> 4;
        float4 v = *(const float4*)(in + b * DL + (j4 << 2));
        int j = j4 << 2;
        sin_t[(j + 0) * BB + b] = v.x;
        sin_t[(j + 1) * BB + b] = v.y;
        sin_t[(j + 2) * BB + b] = v.z;
        sin_t[(j + 3) * BB + b] = v.w;
    }
    __syncthreads();
    int b = tid & 15;
    int o = bid * 16 + (tid >> 4);
    const float4* wr = (const float4*)(W + (size_t)o * DL);
    float a0 = 0.f, a1 = 0.f, a2 = 0.f, a3 = 0.f;
#pragma unroll 16
    for (int j4 = 0; j4 < DL / 4; j4++) {
        float4 wv = __ldg(wr + j4);
        int j = j4 << 2;
        a0 = fmaf(sin_t[(j + 0) * BB + b], wv.x, a0);
        a1 = fmaf(sin_t[(j + 1) * BB + b], wv.y, a1);
        a2 = fmaf(sin_t[(j + 2) * BB + b], wv.z, a2);
        a3 = fmaf(sin_t[(j + 3) * BB + b], wv.w, a3);
    }
    float r = ((a0 + a1) + (a2 + a3)) * C_LIN + bias[o];
    if (mode < 2) r = (r >= 0.f) ? r : pa[o] * r;
    out[b * DL + o] = r;
}

// ---------------- kernel B: mod_pad (3D grid, z<16) + sigma (z==16) ------------------------
__global__ void modpad_sigma(const float* __restrict__ x) {
    __shared__ float smem_u[DL * BB];   // 32KB union
    int tid = threadIdx.x;  // 256
    if (blockIdx.z == 16) {
        int ob = blockIdx.y * 8 + blockIdx.x;
        if (ob >= 32) return;
        float* st2 = smem_u;   // [i][b]
#pragma unroll
        for (int t = 0; t < 8; t++) {
            int idx = tid + t * 256;
            int b = idx & 15, j4 = idx >> 4;
            float4 v = *(const float4*)(g_style + b * CI + (j4 << 2));
            int i = j4 << 2;
            st2[(i + 0) * BB + b] = v.x * v.x;
            st2[(i + 1) * BB + b] = v.y * v.y;
            st2[(i + 2) * BB + b] = v.z * v.z;
            st2[(i + 3) * BB + b] = v.w * v.w;
        }
        __syncthreads();
        int b = tid & 15;
        int o = ob * 16 + (tid >> 4);
        const float4* wr = (const float4*)(g_wsq + (size_t)o * CI);
        float a0 = 0.f, a1 = 0.f, a2 = 0.f, a3 = 0.f;
#pragma unroll 16
        for (int j4 = 0; j4 < CI / 4; j4++) {
            float4 wv = __ldg(wr + j4);
            int i = j4 << 2;
            a0 = fmaf(st2[(i + 0) * BB + b], wv.x, a0);
            a1 = fmaf(st2[(i + 1) * BB + b], wv.y, a1);
            a2 = fmaf(st2[(i + 2) * BB + b], wv.z, a2);
            a3 = fmaf(st2[(i + 3) * BB + b], wv.w, a3);
        }
        float acc = (a0 + a1) + (a2 + a3);
        g_sout[b * CO + o] = C_CONV * rsqrtf(C_CONV * C_CONV * acc + 1e-8f);
        return;
    }
    // ---- mod_pad: modulate + edge-pad + NCHW->NHWC fp16 (16B stores)
    float (*sx)[65] = (float(*)[65])smem_u;
    float* sst = smem_u + 64 * 65;
    int i0 = blockIdx.x << 6;
    int hp = blockIdx.y;
    int b  = blockIdx.z;
    int h = hp - 1; h = h < 0 ? 0 : (h > 63 ? 63 : h);
    const float* xb = x + (((size_t)b * CI + i0) * 64 + h) * 64;
#pragma unroll
    for (int t = 0; t < 4; t++) {
        int idx = tid + t * 256;
        int i = idx >> 4, w4 = (idx & 15) << 2;
        float4 v = *(const float4*)(xb + (size_t)i * 4096 + w4);
        sx[i][w4] = v.x; sx[i][w4 + 1] = v.y; sx[i][w4 + 2] = v.z; sx[i][w4 + 3] = v.w;
    }
    if (tid < 64) sst[tid] = g_style[b * CI + i0 + tid];
    __syncthreads();
    __half* outp = g_xp + (((size_t)b * HPAD + hp) * HPAD) * CI + i0;
    for (int idx = tid; idx < 66 * 8; idx += 256) {   // (wp, 8-ch group)
        int wp = idx >> 3;
        int ip = (idx & 7) << 3;
        int w = wp - 1; w = w < 0 ? 0 : (w > 63 ? 63 : w);
        __half2 h0 = __floats2half2_rn(sx[ip + 0][w] * sst[ip + 0], sx[ip + 1][w] * sst[ip + 1]);
        __half2 h1 = __floats2half2_rn(sx[ip + 2][w] * sst[ip + 2], sx[ip + 3][w] * sst[ip + 3]);
        __half2 h2 = __floats2half2_rn(sx[ip + 4][w] * sst[ip + 4], sx[ip + 5][w] * sst[ip + 5]);
        __half2 h3 = __floats2half2_rn(sx[ip + 6][w] * sst[ip + 6], sx[ip + 7][w] * sst[ip + 7]);
        uint4 v;
        v.x = *(uint32_t*)&h0; v.y = *(uint32_t*)&h1;
        v.z = *(uint32_t*)&h2; v.w = *(uint32_t*)&h3;
        *(uint4*)(outp + (size_t)wp * CI + ip) = v;
    }
}

// ---------------- kernel C: conv, 2 CTAs/SM, tap-granularity pipeline ----------------------
// CTA: 128 threads (4 warps, 2M x 2N), tile M=128 x N=128 (2 image rows).
// 72 iterations t=(cc,dh,dw), cc outer. A: one tap 16KB/iter (dual). B: 2-row slab
// (132 cells) per (cc,dh), reused across 3 dw (dual). 2048 CTAs, occupancy 2/SM.
#define A_ST 16384u
#define B_ST 17408u                       // 132 cells x 128B, padded to 1KB multiple
#define SOFF_B (2u * A_ST)                // 32768
#define SMEM_BYTES (SOFF_B + 2u * B_ST)   // 67584

__device__ __forceinline__ void load_A(int tid, uint32_t sbase, int stage, int tap, int cc,
                                       int o0) {
    uint32_t sA = sbase + (uint32_t)stage * A_ST;
    int idx = tid;               // 1024 pieces / 128 threads = 8
#pragma unroll
    for (int t = 0; t < 8; t++, idx += 128) {
        int row = idx >> 3;
        int pc  = idx & 7;
        const __half* g = g_wh + (((size_t)(tap * 512 + o0 + row)) << 9) + (cc << 6) + (pc << 3);
        CP16(sA + swz(((uint32_t)row << 7) + ((uint32_t)pc << 4)), g);
    }
}

__device__ __forceinline__ void load_B(int tid, uint32_t sbase, int stage, int cc, int dh,
                                       int h0, const __half* __restrict__ xpb) {
    uint32_t sB = sbase + SOFF_B + (uint32_t)stage * B_ST;
    const __half* gb = xpb + (((size_t)((h0 + dh) * HPAD)) << 9) + (cc << 6);
    for (int idx = tid; idx < 1056; idx += 128) {   // 132 cells x 8 pieces
        int cell = idx >> 3;
        int pc   = idx & 7;
        CP16(sB + swz(((uint32_t)cell << 7) + ((uint32_t)pc << 4)),
             gb + (((size_t)cell) << 9) + (pc << 3));
    }
}

__global__ void __launch_bounds__(128, 2) conv_kernel(float* __restrict__ out) {
    extern __shared__ char smem[];
    const uint32_t sbase = smem_u32(smem);
    int tid  = threadIdx.x;
    int w    = tid >> 5;
    int lane = tid & 31;
    int m0w  = (w & 1) << 6;    // warp M offset 0/64
    int nrow = (w >> 1);        // warp image-row within tile (0/1)

    int tile = blockIdx.x;
    int nt = tile & 31;
    int ot = (tile >> 5) & 3;
    int b  = tile >> 7;
    int o0 = ot << 7;
    int n0 = nt << 7;           // pixel offset (2 rows x 64)
    int h0 = nt << 1;           // image row offset

    const __half* xpb = g_xp + (size_t)b * (HPAD * HPAD * CI);

    float acc[4][8][4];
#pragma unroll
    for (int i = 0; i < 4; i++)
#pragma unroll
        for (int jn = 0; jn < 8; jn++)
#pragma unroll
            for (int c = 0; c < 4; c++) acc[i][jn][c] = 0.f;

    uint32_t rowA  = (uint32_t)(m0w + (lane & 15));
    uint32_t kselA = (uint32_t)((lane >> 4) << 4);
    uint32_t lp    = (uint32_t)((lane & 7) + ((lane & 16) >> 1));
    uint32_t kselB = (uint32_t)((lane & 8) << 1);

    // prologue: B slab (cc0,dh0) + A tap0
    load_B(tid, sbase, 0, 0, 0, h0, xpb);
    load_A(tid, sbase, 0, 0, 0, o0);
    CP_COMMIT();

    int cc = 0, dh = 0, dw = 0, bst = 0;
    for (int t = 0; t < 72; t++) {
        __syncthreads();                 // all warps done with buffers being overwritten
        int dwn = dw + 1, dhn = dh, ccn = cc;
        if (dwn == 3) { dwn = 0; dhn++; if (dhn == 3) { dhn = 0; ccn++; } }
        if (t < 71) {
            load_A(tid, sbase, (t + 1) & 1, dhn * 3 + dwn, ccn, o0);
            if (dwn == 0) load_B(tid, sbase, bst ^ 1, ccn, dhn, h0, xpb);
        }
        CP_COMMIT();
        CP_WAIT(1);                      // data for iteration t complete
        __syncthreads();

        uint32_t sA = sbase + (uint32_t)(t & 1) * A_ST;
        uint32_t sB = sbase + SOFF_B + (uint32_t)bst * B_ST;
        uint32_t cell0 = (uint32_t)(nrow * 66) + lp + (uint32_t)dw;
#pragma unroll
        for (int kk = 0; kk < 4; kk++) {
            uint32_t kb = (uint32_t)(kk << 5);
            uint32_t a[4][4];
#pragma unroll
            for (int mi = 0; mi < 4; mi++)
                ldsm_x4(a[mi][0], a[mi][1], a[mi][2], a[mi][3],
                        sA + swz(((rowA + (mi << 4)) << 7) + kb + kselA));
            uint32_t bf[4][4];
#pragma unroll
            for (int jj = 0; jj < 4; jj++)
                ldsm_x4(bf[jj][0], bf[jj][1], bf[jj][2], bf[jj][3],
                        sB + swz(((cell0 + (jj << 4)) << 7) + kb + kselB));
#pragma unroll
            for (int mi = 0; mi < 4; mi++)
#pragma unroll
                for (int jn = 0; jn < 8; jn++)
                    mma16816(acc[mi][jn], a[mi], bf[jn >> 1][(jn & 1) << 1],
                             bf[jn >> 1][((jn & 1) << 1) + 1]);
        }
        if (dwn == 0) bst ^= 1;          // next iteration uses the other B slab
        dw = dwn; dh = dhn; cc = ccn;
    }

    // epilogue: scale by sout[b][o], streaming fp32 stores
    int n0w = nrow << 6;
    const float* svb = g_sout + (b << 9) + o0;
#pragma unroll
    for (int mi = 0; mi < 4; mi++) {
        int r0 = m0w + (mi << 4) + (lane >> 2);
        float sv0 = svb[r0];
        float sv1 = svb[r0 + 8];
        float* p0 = out + (((size_t)((b << 9) + o0 + r0)) << 12) + n0 + n0w;
        float* p1 = p0 + ((size_t)8 << 12);
#pragma unroll
        for (int jp = 0; jp < 4; jp++) {
            int jn = jp << 1;
            int c = (jp << 4) + ((lane & 3) << 1);
            float2 v00 = make_float2(acc[mi][jn][0] * sv0, acc[mi][jn][1] * sv0);
            float2 v01 = make_float2(acc[mi][jn + 1][0] * sv0, acc[mi][jn + 1][1] * sv0);
            float2 v10 = make_float2(acc[mi][jn][2] * sv1, acc[mi][jn][3] * sv1);
            float2 v11 = make_float2(acc[mi][jn + 1][2] * sv1, acc[mi][jn + 1][3] * sv1);
            asm volatile("st.global.cs.v2.f32 [%0], {%1,%2};" :: "l"(p0 + c),     "f"(v00.x), "f"(v00.y));
            asm volatile("st.global.cs.v2.f32 [%0], {%1,%2};" :: "l"(p0 + c + 8), "f"(v01.x), "f"(v01.y));
            asm volatile("st.global.cs.v2.f32 [%0], {%1,%2};" :: "l"(p1 + c),     "f"(v10.x), "f"(v10.y));
            asm volatile("st.global.cs.v2.f32 [%0], {%1,%2};" :: "l"(p1 + c + 8), "f"(v11.x), "f"(v11.y));
        }
    }
}

// ---------------- launch ----------------
extern "C" void kernel_launch(void* const* d_in, const int* in_sizes, int n_in,
                              void* d_out, int out_size) {
    (void)in_sizes; (void)n_in; (void)out_size;
    const float* x  = (const float*)d_in[0];
    const float* s  = (const float*)d_in[1];
    const float* w0 = (const float*)d_in[2];
    const float* b0 = (const float*)d_in[3];
    const float* a0 = (const float*)d_in[4];
    const float* w1 = (const float*)d_in[5];
    const float* b1 = (const float*)d_in[6];
    const float* a1 = (const float*)d_in[7];
    const float* sw = (const float*)d_in[8];
    const float* sb = (const float*)d_in[9];
    const float* cw = (const float*)d_in[10];
    float* out = (float*)d_out;

    cudaFuncSetAttribute(conv_kernel, cudaFuncAttributeMaxDynamicSharedMemorySize, SMEM_BYTES);

    lin_wp<<<32 + 1024, 256>>>(s, w0, b0, a0, cw, 0);          // layer 0 + weight prep
    lin_wp<<<32, 256>>>(nullptr, w1, b1, a1, nullptr, 1);      // layer 1
    lin_wp<<<32, 256>>>(nullptr, sw, sb, nullptr, nullptr, 2); // style layer
    modpad_sigma<<<dim3(8, 66, 17), 256>>>(x);                 // modulate/pad + sigma
    conv_kernel<<<BB * 4 * 32, 128, SMEM_BYTES>>>(out);
}

// round 9
// speedup vs baseline: 1.0581x; 1.0581x over previous
#include <cuda_runtime.h>
#include <cuda_fp16.h>
#include <cstdint>

// ---------------- problem sizes ----------------
#define BB   16
#define CI   512
#define CO   512
#define HW_  64
#define DL   512
#define HPAD 66

#define C_LIN  0.044194173824159216f   // 1/sqrt(512)
#define C_CONV 0.014731391274719739f   // 1/sqrt(512*9)

// ---------------- device scratch ----------------
__device__ __half g_wh[9 * CO * CI];                   // weights fp16, tap-major [9][CO][CI]
__device__ float  g_wsq[CO * CI];                      // sum_k conv_w^2
__device__ float  g_z0[BB * DL];
__device__ float  g_z1[BB * DL];
__device__ float  g_style[BB * CI];
__device__ float  g_sout[BB * CO];                     // c_conv * sigma_inv
__device__ __half g_xp[(size_t)BB * HPAD * HPAD * CI]; // NHWC padded modulated input

// ---------------- helpers ----------------
__device__ __forceinline__ uint32_t smem_u32(const void* p) {
    uint32_t a;
    asm("{ .reg .u64 t; cvta.to.shared.u64 t, %1; cvt.u32.u64 %0, t; }" : "=r"(a) : "l"(p));
    return a;
}

__device__ __forceinline__ uint32_t swz(uint32_t x) { return x ^ ((x >> 3) & 0x70); }

#define CP16(smem, gptr) \
    asm volatile("cp.async.cg.shared.global [%0], [%1], 16;" :: "r"(smem), "l"(gptr))
#define CP_COMMIT() asm volatile("cp.async.commit_group;" ::: "memory")
#define CP_WAIT(n)  asm volatile("cp.async.wait_group %0;" :: "n"(n) : "memory")

__device__ __forceinline__ void ldsm_x4(uint32_t& r0, uint32_t& r1, uint32_t& r2, uint32_t& r3,
                                        uint32_t addr) {
    asm volatile("ldmatrix.sync.aligned.m8n8.x4.shared.b16 {%0,%1,%2,%3}, [%4];"
                 : "=r"(r0), "=r"(r1), "=r"(r2), "=r"(r3) : "r"(addr));
}

__device__ __forceinline__ void mma16816(float* c, const uint32_t* a, uint32_t b0, uint32_t b1) {
    asm volatile(
        "mma.sync.aligned.m16n8k16.row.col.f32.f16.f16.f32 "
        "{%0,%1,%2,%3}, {%4,%5,%6,%7}, {%8,%9}, {%0,%1,%2,%3};"
        : "+f"(c[0]), "+f"(c[1]), "+f"(c[2]), "+f"(c[3])
        : "r"(a[0]), "r"(a[1]), "r"(a[2]), "r"(a[3]), "r"(b0), "r"(b1));
}

// ---------------- kernel A: linear layer (32 blocks) + optional weight prep ----------------
__global__ void lin_wp(const float* __restrict__ ext_in, const float* __restrict__ W,
                       const float* __restrict__ bias, const float* __restrict__ pa,
                       const float* __restrict__ cw, int mode) {
    int bid = blockIdx.x;
    int tid = threadIdx.x;  // 256
    if (bid >= 32) {
        int g = (bid - 32) * 256 + tid;
        const float* p = cw + (size_t)g * 9;
        float sq = 0.f;
#pragma unroll
        for (int k = 0; k < 9; k++) {
            float v = p[k];
            sq = fmaf(v, v, sq);
            g_wh[(size_t)k * (CO * CI) + g] = __float2half(v);
        }
        g_wsq[g] = sq;
        return;
    }
    __shared__ float sin_t[DL * BB];   // transposed [j][b], 32KB
    const float* in = (mode == 0) ? ext_in : (mode == 1 ? g_z0 : g_z1);
    float* out      = (mode == 0) ? g_z0   : (mode == 1 ? g_z1 : g_style);
#pragma unroll
    for (int t = 0; t < 8; t++) {
        int idx = tid + t * 256;
        int b = idx & 15, j4 = idx >> 4;
        float4 v = *(const float4*)(in + b * DL + (j4 << 2));
        int j = j4 << 2;
        sin_t[(j + 0) * BB + b] = v.x;
        sin_t[(j + 1) * BB + b] = v.y;
        sin_t[(j + 2) * BB + b] = v.z;
        sin_t[(j + 3) * BB + b] = v.w;
    }
    __syncthreads();
    int b = tid & 15;
    int o = bid * 16 + (tid >> 4);
    const float4* wr = (const float4*)(W + (size_t)o * DL);
    float a0 = 0.f, a1 = 0.f, a2 = 0.f, a3 = 0.f;
#pragma unroll 16
    for (int j4 = 0; j4 < DL / 4; j4++) {
        float4 wv = __ldg(wr + j4);
        int j = j4 << 2;
        a0 = fmaf(sin_t[(j + 0) * BB + b], wv.x, a0);
        a1 = fmaf(sin_t[(j + 1) * BB + b], wv.y, a1);
        a2 = fmaf(sin_t[(j + 2) * BB + b], wv.z, a2);
        a3 = fmaf(sin_t[(j + 3) * BB + b], wv.w, a3);
    }
    float r = ((a0 + a1) + (a2 + a3)) * C_LIN + bias[o];
    if (mode < 2) r = (r >= 0.f) ? r : pa[o] * r;
    out[b * DL + o] = r;
}

// ---------------- kernel B: mod_pad (3D grid, z<16) + sigma (z==16) ------------------------
__global__ void modpad_sigma(const float* __restrict__ x) {
    __shared__ float smem_u[DL * BB];   // 32KB union
    int tid = threadIdx.x;  // 256
    if (blockIdx.z == 16) {
        int ob = blockIdx.y * 8 + blockIdx.x;
        if (ob >= 32) return;
        float* st2 = smem_u;   // [i][b]
#pragma unroll
        for (int t = 0; t < 8; t++) {
            int idx = tid + t * 256;
            int b = idx & 15, j4 = idx >> 4;
            float4 v = *(const float4*)(g_style + b * CI + (j4 << 2));
            int i = j4 << 2;
            st2[(i + 0) * BB + b] = v.x * v.x;
            st2[(i + 1) * BB + b] = v.y * v.y;
            st2[(i + 2) * BB + b] = v.z * v.z;
            st2[(i + 3) * BB + b] = v.w * v.w;
        }
        __syncthreads();
        int b = tid & 15;
        int o = ob * 16 + (tid >> 4);
        const float4* wr = (const float4*)(g_wsq + (size_t)o * CI);
        float a0 = 0.f, a1 = 0.f, a2 = 0.f, a3 = 0.f;
#pragma unroll 16
        for (int j4 = 0; j4 < CI / 4; j4++) {
            float4 wv = __ldg(wr + j4);
            int i = j4 << 2;
            a0 = fmaf(st2[(i + 0) * BB + b], wv.x, a0);
            a1 = fmaf(st2[(i + 1) * BB + b], wv.y, a1);
            a2 = fmaf(st2[(i + 2) * BB + b], wv.z, a2);
            a3 = fmaf(st2[(i + 3) * BB + b], wv.w, a3);
        }
        float acc = (a0 + a1) + (a2 + a3);
        g_sout[b * CO + o] = C_CONV * rsqrtf(C_CONV * C_CONV * acc + 1e-8f);
        return;
    }
    // ---- mod_pad: modulate + edge-pad + NCHW->NHWC fp16 (16B stores)
    float (*sx)[65] = (float(*)[65])smem_u;
    float* sst = smem_u + 64 * 65;
    int i0 = blockIdx.x << 6;
    int hp = blockIdx.y;
    int b  = blockIdx.z;
    int h = hp - 1; h = h < 0 ? 0 : (h > 63 ? 63 : h);
    const float* xb = x + (((size_t)b * CI + i0) * 64 + h) * 64;
#pragma unroll
    for (int t = 0; t < 4; t++) {
        int idx = tid + t * 256;
        int i = idx >> 4, w4 = (idx & 15) << 2;
        float4 v = *(const float4*)(xb + (size_t)i * 4096 + w4);
        sx[i][w4] = v.x; sx[i][w4 + 1] = v.y; sx[i][w4 + 2] = v.z; sx[i][w4 + 3] = v.w;
    }
    if (tid < 64) sst[tid] = g_style[b * CI + i0 + tid];
    __syncthreads();
    __half* outp = g_xp + (((size_t)b * HPAD + hp) * HPAD) * CI + i0;
    for (int idx = tid; idx < 66 * 8; idx += 256) {   // (wp, 8-ch group)
        int wp = idx >> 3;
        int ip = (idx & 7) << 3;
        int w = wp - 1; w = w < 0 ? 0 : (w > 63 ? 63 : w);
        __half2 h0 = __floats2half2_rn(sx[ip + 0][w] * sst[ip + 0], sx[ip + 1][w] * sst[ip + 1]);
        __half2 h1 = __floats2half2_rn(sx[ip + 2][w] * sst[ip + 2], sx[ip + 3][w] * sst[ip + 3]);
        __half2 h2 = __floats2half2_rn(sx[ip + 4][w] * sst[ip + 4], sx[ip + 5][w] * sst[ip + 5]);
        __half2 h3 = __floats2half2_rn(sx[ip + 6][w] * sst[ip + 6], sx[ip + 7][w] * sst[ip + 7]);
        uint4 v;
        v.x = *(uint32_t*)&h0; v.y = *(uint32_t*)&h1;
        v.z = *(uint32_t*)&h2; v.w = *(uint32_t*)&h3;
        *(uint4*)(outp + (size_t)wp * CI + ip) = v;
    }
}

// ---------------- kernel C: conv, tap-slab implicit GEMM (R6 config, nt-major order) -------
// CTA tile M=128 x N=256 (4 image rows). 24 super-chunks = 3 tap-rows(dh) x 8 ch-chunks(cc).
// Per super-chunk: B slab 4x66x64ch (33792B, serves dw=0,1,2) + A 3 taps x 16KB.
// 8 warps (2 M x 4 N), warp tile 64x64. 1 CTA/SM, 2-stage uniform pipeline.
#define A_BYTES   49152u            // 3 x 16KB
#define B_BYTES   33792u            // 264 cells x 128B
#define STAGE_BYTES (A_BYTES + B_BYTES)   // 82944
#define SMEM_BYTES (2u * STAGE_BYTES)     // 165888
#define NSUP 24

__device__ __forceinline__ void load_super(int tid, uint32_t sbase, int stage, int s,
                                           int o0, int h0, const __half* __restrict__ xpb) {
    uint32_t sA = sbase + (uint32_t)stage * STAGE_BYTES;
    uint32_t sB = sA + A_BYTES;
    int dh = s >> 3;
    int cc = s & 7;
    {
        int idx = tid;               // 3072 pieces / 256 threads = 12
#pragma unroll
        for (int t = 0; t < 12; t++, idx += 256) {
            int dw   = idx >> 10;
            int row  = (idx >> 3) & 127;
            int pc   = idx & 7;
            int tap  = dh * 3 + dw;
            const __half* g = g_wh + (((size_t)(tap * 512 + o0 + row)) << 9) + (cc << 6) + (pc << 3);
            CP16(sA + (uint32_t)dw * 16384u + swz(((uint32_t)row << 7) + ((uint32_t)pc << 4)), g);
        }
    }
    {
        int h0s = h0 + dh;
        const __half* gb = xpb + (((size_t)(h0s * HPAD)) << 9) + (cc << 6);
        for (int idx = tid; idx < 2112; idx += 256) {    // 264 cells x 8 pieces
            int cell = idx >> 3;
            int pc   = idx & 7;
            CP16(sB + swz(((uint32_t)cell << 7) + ((uint32_t)pc << 4)),
                 gb + (((size_t)cell) << 9) + (pc << 3));
        }
    }
}

__global__ void __launch_bounds__(256, 1) conv_kernel(float* __restrict__ out) {
    extern __shared__ char smem[];
    const uint32_t sbase = smem_u32(smem);
    int tid  = threadIdx.x;
    int w    = tid >> 5;
    int lane = tid & 31;
    int m0w  = (w & 1) << 6;
    int nrow = (w >> 1);

    // nt-major CTA order: 4 consecutive CTAs share the same B slabs (different o-chunks)
    int tile = blockIdx.x;
    int ot = tile & 3;
    int nt = (tile >> 2) & 15;
    int b  = tile >> 6;
    int o0 = ot << 7;
    int n0 = nt << 8;
    int h0 = nt << 2;

    const __half* xpb = g_xp + (size_t)b * (HPAD * HPAD * CI);

    float acc[4][8][4];
#pragma unroll
    for (int i = 0; i < 4; i++)
#pragma unroll
        for (int jn = 0; jn < 8; jn++)
#pragma unroll
            for (int c = 0; c < 4; c++) acc[i][jn][c] = 0.f;

    uint32_t rowA  = (uint32_t)(m0w + (lane & 15));
    uint32_t kselA = (uint32_t)((lane >> 4) << 4);
    uint32_t lp    = (uint32_t)((lane & 7) + ((lane & 16) >> 1));
    uint32_t kselB = (uint32_t)((lane & 8) << 1);

    load_super(tid, sbase, 0, 0, o0, h0, xpb);
    CP_COMMIT();

    for (int s = 0; s < NSUP; s++) {
        int st = s & 1;
        __syncthreads();
        if (s + 1 < NSUP)
            load_super(tid, sbase, (s + 1) & 1, s + 1, o0, h0, xpb);
        CP_COMMIT();
        CP_WAIT(1);
        __syncthreads();

        uint32_t sA = sbase + (uint32_t)st * STAGE_BYTES;
        uint32_t sB = sA + A_BYTES;
#pragma unroll
        for (int dw = 0; dw < 3; dw++) {
            uint32_t sAd = sA + (uint32_t)dw * 16384u;
            uint32_t cell0 = (uint32_t)(nrow * 66) + lp + (uint32_t)dw;
#pragma unroll
            for (int kk = 0; kk < 4; kk++) {
                uint32_t kb = (uint32_t)(kk << 5);
                uint32_t a[4][4];
#pragma unroll
                for (int mi = 0; mi < 4; mi++)
                    ldsm_x4(a[mi][0], a[mi][1], a[mi][2], a[mi][3],
                            sAd + swz(((rowA + (mi << 4)) << 7) + kb + kselA));
                uint32_t bf[4][4];
#pragma unroll
                for (int jj = 0; jj < 4; jj++)
                    ldsm_x4(bf[jj][0], bf[jj][1], bf[jj][2], bf[jj][3],
                            sB + swz(((cell0 + (jj << 4)) << 7) + kb + kselB));
#pragma unroll
                for (int mi = 0; mi < 4; mi++)
#pragma unroll
                    for (int jn = 0; jn < 8; jn++)
                        mma16816(acc[mi][jn], a[mi], bf[jn >> 1][(jn & 1) << 1],
                                 bf[jn >> 1][((jn & 1) << 1) + 1]);
            }
        }
    }

    // epilogue: scale by sout[b][o], streaming fp32 stores
    int n0w = nrow << 6;
    const float* svb = g_sout + (b << 9) + o0;
#pragma unroll
    for (int mi = 0; mi < 4; mi++) {
        int r0 = m0w + (mi << 4) + (lane >> 2);
        float sv0 = svb[r0];
        float sv1 = svb[r0 + 8];
        float* p0 = out + (((size_t)((b << 9) + o0 + r0)) << 12) + n0 + n0w;
        float* p1 = p0 + ((size_t)8 << 12);
#pragma unroll
        for (int jp = 0; jp < 4; jp++) {
            int jn = jp << 1;
            int c = (jp << 4) + ((lane & 3) << 1);
            float2 v00 = make_float2(acc[mi][jn][0] * sv0, acc[mi][jn][1] * sv0);
            float2 v01 = make_float2(acc[mi][jn + 1][0] * sv0, acc[mi][jn + 1][1] * sv0);
            float2 v10 = make_float2(acc[mi][jn][2] * sv1, acc[mi][jn][3] * sv1);
            float2 v11 = make_float2(acc[mi][jn + 1][2] * sv1, acc[mi][jn + 1][3] * sv1);
            asm volatile("st.global.cs.v2.f32 [%0], {%1,%2};" :: "l"(p0 + c),     "f"(v00.x), "f"(v00.y));
            asm volatile("st.global.cs.v2.f32 [%0], {%1,%2};" :: "l"(p0 + c + 8), "f"(v01.x), "f"(v01.y));
            asm volatile("st.global.cs.v2.f32 [%0], {%1,%2};" :: "l"(p1 + c),     "f"(v10.x), "f"(v10.y));
            asm volatile("st.global.cs.v2.f32 [%0], {%1,%2};" :: "l"(p1 + c + 8), "f"(v11.x), "f"(v11.y));
        }
    }
}

// ---------------- launch ----------------
extern "C" void kernel_launch(void* const* d_in, const int* in_sizes, int n_in,
                              void* d_out, int out_size) {
    (void)in_sizes; (void)n_in; (void)out_size;
    const float* x  = (const float*)d_in[0];
    const float* s  = (const float*)d_in[1];
    const float* w0 = (const float*)d_in[2];
    const float* b0 = (const float*)d_in[3];
    const float* a0 = (const float*)d_in[4];
    const float* w1 = (const float*)d_in[5];
    const float* b1 = (const float*)d_in[6];
    const float* a1 = (const float*)d_in[7];
    const float* sw = (const float*)d_in[8];
    const float* sb = (const float*)d_in[9];
    const float* cw = (const float*)d_in[10];
    float* out = (float*)d_out;

    cudaFuncSetAttribute(conv_kernel, cudaFuncAttributeMaxDynamicSharedMemorySize, SMEM_BYTES);

    lin_wp<<<32 + 1024, 256>>>(s, w0, b0, a0, cw, 0);          // layer 0 + weight prep
    lin_wp<<<32, 256>>>(nullptr, w1, b1, a1, nullptr, 1);      // layer 1
    lin_wp<<<32, 256>>>(nullptr, sw, sb, nullptr, nullptr, 2); // style layer
    modpad_sigma<<<dim3(8, 66, 17), 256>>>(x);                 // modulate/pad + sigma
    conv_kernel<<<BB * 4 * 16, 256, SMEM_BYTES>>>(out);
}